// round 1
// baseline (speedup 1.0000x reference)
#include <cuda_runtime.h>

// InteractionBlock: n=1e6, F=128, NL=4, M_TOT=16, C=F+NL=132
//   d_chi[i,l] = sum_{m:SEG[m]=l} chi[i,m]^2
//   y = [x, d_chi]  (132)
//   h = y @ W + b   (W: 132x132 row-major)
//   a1 = h[:, :128]; chi_out[:, m] = h[:, 128+SEG[m]] * chi[:, m]
// Output: [a1 (n*128) | chi_out (n*16)] float32

#define FDIM 128
#define CDIM 132
#define KP   136   // padded K (rows of W)
#define CP   136   // padded cols of W
#define ROWS 64    // rows per block tile
#define NTHREADS 544  // 16 rowgroups x 34 colgroups

// smem floats: ws[KP][CP] + ys[KP][64] + chis[64][16] + bs[CP]
#define WS_FLOATS  (KP * CP)       // 18496
#define YS_FLOATS  (KP * 64)       // 8704
#define CHIS_FLOATS (ROWS * 16)    // 1024
#define BS_FLOATS  (CP)            // 136
#define SMEM_FLOATS (WS_FLOATS + YS_FLOATS + CHIS_FLOATS + BS_FLOATS)
#define SMEM_BYTES (SMEM_FLOATS * 4)

__device__ __forceinline__ unsigned long long pk2(float lo, float hi) {
    unsigned long long r;
    asm("mov.b64 %0, {%1, %2};" : "=l"(r) : "f"(lo), "f"(hi));
    return r;
}
__device__ __forceinline__ unsigned long long fma2(unsigned long long a,
                                                   unsigned long long b,
                                                   unsigned long long c) {
    unsigned long long d;
    asm("fma.rn.f32x2 %0, %1, %2, %3;" : "=l"(d) : "l"(a), "l"(b), "l"(c));
    return d;
}
__device__ __forceinline__ float2 upk2(unsigned long long v) {
    float2 f;
    asm("mov.b64 {%0, %1}, %2;" : "=f"(f.x), "=f"(f.y) : "l"(v));
    return f;
}

__global__ void __launch_bounds__(NTHREADS, 1)
ib_kernel(const float* __restrict__ x,
          const float* __restrict__ chi,
          const float* __restrict__ W,
          const float* __restrict__ b,
          float* __restrict__ out_a1,
          float* __restrict__ out_chi,
          int n)
{
    extern __shared__ float smem[];
    float* ws   = smem;                       // [KP][CP]
    float* ys   = ws + WS_FLOATS;             // [KP][64]  (group-rotated)
    float* chis = ys + YS_FLOATS;             // [64][16]
    float* bs   = chis + CHIS_FLOATS;         // [CP]

    const int tid  = threadIdx.x;
    const int row0 = blockIdx.x * ROWS;

    // ---- stage W (zero-padded to [KP][CP]) ----
    for (int i = tid; i < KP * (CP / 4); i += NTHREADS) {
        int kk = i / 34;
        int cp = i - kk * 34;
        float4 v = make_float4(0.f, 0.f, 0.f, 0.f);
        if (kk < CDIM && cp < 33)
            v = *reinterpret_cast<const float4*>(W + kk * CDIM + cp * 4);
        *reinterpret_cast<float4*>(ws + kk * CP + cp * 4) = v;
    }

    // ---- stage bias (zero-padded) ----
    if (tid < 34) {
        float4 v = make_float4(0.f, 0.f, 0.f, 0.f);
        if (tid < 33) v = *reinterpret_cast<const float4*>(b + tid * 4);
        *reinterpret_cast<float4*>(bs + tid * 4) = v;
    }

    // ---- stage chi rows ----
    for (int i = tid; i < ROWS * 4; i += NTHREADS) {
        int r = i >> 2, q = i & 3;
        float4 v = make_float4(0.f, 0.f, 0.f, 0.f);
        if (row0 + r < n)
            v = *reinterpret_cast<const float4*>(chi + (size_t)(row0 + r) * 16 + q * 4);
        *reinterpret_cast<float4*>(chis + r * 16 + q * 4) = v;
    }

    // ---- stage x transposed into ys with group rotation ----
    // row r at k stored at word k*64 + (((r>>2) + (k>>2)) & 15)*4 + (r&3)
    for (int i = tid; i < ROWS * 32; i += NTHREADS) {
        int r = i >> 5, kg = i & 31;
        float4 v = make_float4(0.f, 0.f, 0.f, 0.f);
        if (row0 + r < n)
            v = *reinterpret_cast<const float4*>(x + (size_t)(row0 + r) * FDIM + kg * 4);
        int rg = r >> 2, rr = r & 3;
        int g = (rg + kg) & 15;
        float* base = ys + ((4 * kg) * 64 + g * 4 + rr);
        base[0]   = v.x;
        base[64]  = v.y;
        base[128] = v.z;
        base[192] = v.w;
    }
    __syncthreads();

    // ---- d_chi into ys rows k=128..131, zeros for 132..135 ----
    for (int i = tid; i < ROWS * 8; i += NTHREADS) {
        int r = i >> 3, kq = i & 7;
        int k = 128 + kq;
        float vsum = 0.f;
        if (kq < 4) {
            const int lo[4] = {0, 1, 4, 9};
            const int hi[4] = {1, 4, 9, 16};
            #pragma unroll 1
            for (int m = lo[kq]; m < hi[kq]; ++m) {
                float c = chis[r * 16 + m];
                vsum += c * c;
            }
        }
        int rg = r >> 2, rr = r & 3;
        int g = (rg + (k >> 2)) & 15;
        ys[k * 64 + g * 4 + rr] = vsum;
    }
    __syncthreads();

    // ---- mainloop: 4 rows x 4 cols register tile, f32x2 packed FMA ----
    const int rg = tid & 15;
    const int cg = tid >> 4;     // 0..33
    const int r0 = rg * 4;
    const int c0 = cg * 4;

    unsigned long long acc[4][2];
    #pragma unroll
    for (int ri = 0; ri < 4; ++ri) { acc[ri][0] = 0ull; acc[ri][1] = 0ull; }

    const float4* wsf4 = reinterpret_cast<const float4*>(ws);  // [k][34]

    #pragma unroll 8
    for (int k = 0; k < KP; ++k) {
        float4 w4 = wsf4[k * 34 + cg];
        float4 y4 = *reinterpret_cast<const float4*>(
            ys + (k << 6) + (((rg + (k >> 2)) & 15) << 2));
        unsigned long long wb0 = pk2(w4.x, w4.y);
        unsigned long long wb1 = pk2(w4.z, w4.w);
        float yv0 = y4.x, yv1 = y4.y, yv2 = y4.z, yv3 = y4.w;
        unsigned long long a0 = pk2(yv0, yv0);
        acc[0][0] = fma2(a0, wb0, acc[0][0]);
        acc[0][1] = fma2(a0, wb1, acc[0][1]);
        unsigned long long a1r = pk2(yv1, yv1);
        acc[1][0] = fma2(a1r, wb0, acc[1][0]);
        acc[1][1] = fma2(a1r, wb1, acc[1][1]);
        unsigned long long a2 = pk2(yv2, yv2);
        acc[2][0] = fma2(a2, wb0, acc[2][0]);
        acc[2][1] = fma2(a2, wb1, acc[2][1]);
        unsigned long long a3 = pk2(yv3, yv3);
        acc[3][0] = fma2(a3, wb0, acc[3][0]);
        acc[3][1] = fma2(a3, wb1, acc[3][1]);
    }

    // ---- epilogue ----
    float4 bb = *reinterpret_cast<const float4*>(bs + c0);

    if (c0 < FDIM) {
        #pragma unroll
        for (int ri = 0; ri < 4; ++ri) {
            int row = row0 + r0 + ri;
            if (row < n) {
                float2 p0 = upk2(acc[ri][0]);
                float2 p1 = upk2(acc[ri][1]);
                float4 h = make_float4(p0.x + bb.x, p0.y + bb.y,
                                       p1.x + bb.z, p1.y + bb.w);
                *reinterpret_cast<float4*>(out_a1 + (size_t)row * FDIM + c0) = h;
            }
        }
    } else if (c0 == FDIM) {
        // cols 128..131 -> b1[l]; chi_out[m] = b1[SEG[m]] * chi[m]
        #pragma unroll
        for (int ri = 0; ri < 4; ++ri) {
            int row = row0 + r0 + ri;
            if (row < n) {
                float2 p0 = upk2(acc[ri][0]);
                float2 p1 = upk2(acc[ri][1]);
                float hl0 = p0.x + bb.x;
                float hl1 = p0.y + bb.y;
                float hl2 = p1.x + bb.z;
                float hl3 = p1.y + bb.w;
                const float* crow = chis + (r0 + ri) * 16;
                float o[16];
                o[0] = hl0 * crow[0];
                #pragma unroll
                for (int m = 1; m < 4; ++m)  o[m] = hl1 * crow[m];
                #pragma unroll
                for (int m = 4; m < 9; ++m)  o[m] = hl2 * crow[m];
                #pragma unroll
                for (int m = 9; m < 16; ++m) o[m] = hl3 * crow[m];
                float* dst = out_chi + (size_t)row * 16;
                #pragma unroll
                for (int q = 0; q < 4; ++q)
                    *reinterpret_cast<float4*>(dst + q * 4) =
                        make_float4(o[q * 4], o[q * 4 + 1], o[q * 4 + 2], o[q * 4 + 3]);
            }
        }
    }
    // cg == 33: padding columns, nothing to write
}

extern "C" void kernel_launch(void* const* d_in, const int* in_sizes, int n_in,
                              void* d_out, int out_size)
{
    // Identify inputs by size (expected order: x, chi, point_mask, W, b)
    int ix = 0, ichi = 1, iW = 3, ib = 4;
    // x = largest buffer
    long long maxsz = -1;
    for (int i = 0; i < n_in; ++i)
        if ((long long)in_sizes[i] > maxsz) { maxsz = in_sizes[i]; ix = i; }
    long long n = maxsz / FDIM;
    for (int i = 0; i < n_in; ++i) {
        long long s = in_sizes[i];
        if (i == ix) continue;
        if (s == CDIM * CDIM) iW = i;
        else if (s == CDIM)   ib = i;
        else if (s == 16 * n) ichi = i;
    }

    const float* x   = (const float*)d_in[ix];
    const float* chi = (const float*)d_in[ichi];
    const float* W   = (const float*)d_in[iW];
    const float* b   = (const float*)d_in[ib];

    float* out_a1  = (float*)d_out;
    float* out_chi = out_a1 + (size_t)n * FDIM;

    cudaFuncSetAttribute(ib_kernel, cudaFuncAttributeMaxDynamicSharedMemorySize,
                         SMEM_BYTES);

    int grid = (int)((n + ROWS - 1) / ROWS);
    ib_kernel<<<grid, NTHREADS, SMEM_BYTES>>>(x, chi, W, b, out_a1, out_chi, (int)n);
}

// round 2
// speedup vs baseline: 1.2675x; 1.2675x over previous
#include <cuda_runtime.h>

// InteractionBlock: n=1e6, F=128, NL=4, M_TOT=16, C=F+NL=132
//   d_chi[i,l] = sum_{m:SEG[m]=l} chi[i,m]^2
//   y = [x, d_chi]  (132)
//   h = y @ W + b   (W: 132x132 row-major)
//   a1 = h[:, :128]; chi_out[:, m] = h[:, 128+SEG[m]] * chi[:, m]
// Output: [a1 (n*128) | chi_out (n*16)] float32

#define FDIM 128
#define CDIM 132
#define KP   136
#define CP   136
#define ROWS 256
#define NTHREADS 544   // 17 warps

// smem: ws[136][136] + ys[136][256] + bs[136]
#define WS_FLOATS  (KP * CP)        // 18496
#define YS_FLOATS  (KP * ROWS)      // 34816
#define BS_FLOATS  (CP)             // 136
#define SMEM_FLOATS (WS_FLOATS + YS_FLOATS + BS_FLOATS)
#define SMEM_BYTES (SMEM_FLOATS * 4)

__device__ __forceinline__ unsigned long long pk2(float lo, float hi) {
    unsigned long long r;
    asm("mov.b64 %0, {%1, %2};" : "=l"(r) : "f"(lo), "f"(hi));
    return r;
}
__device__ __forceinline__ unsigned long long fma2(unsigned long long a,
                                                   unsigned long long b,
                                                   unsigned long long c) {
    unsigned long long d;
    asm("fma.rn.f32x2 %0, %1, %2, %3;" : "=l"(d) : "l"(a), "l"(b), "l"(c));
    return d;
}
__device__ __forceinline__ float2 upk2(unsigned long long v) {
    float2 f;
    asm("mov.b64 {%0, %1}, %2;" : "=f"(f.x), "=f"(f.y) : "l"(v));
    return f;
}

// ys layout: row r (g=r>>3, j=r&7, half=j>>2, jj=j&3), k (q=k>>2):
//   ys[k*256 + half*128 + ((g+q)&31)*4 + jj]
// Mainloop read (lane=g): float4 at k*64 + half*32 + ((g+q)&31)  (conflict-free)

template<int NCJ>
__device__ __forceinline__ void mainloop(const float* ws, const float* ys,
                                         int g, int cg,
                                         unsigned long long acc[8][4])
{
    const float4* ws4 = reinterpret_cast<const float4*>(ws);
    const float4* ys4 = reinterpret_cast<const float4*>(ys);
    #pragma unroll 2
    for (int kq = 0; kq < 34; ++kq) {
        const int rot = (g + kq) & 31;
        #pragma unroll
        for (int c = 0; c < 4; ++c) {
            const int k = 4 * kq + c;
            unsigned long long wb[4];
            float4 w0 = ws4[k * 34 + cg * 2];
            wb[0] = pk2(w0.x, w0.y);
            wb[1] = pk2(w0.z, w0.w);
            if (NCJ == 4) {
                float4 w1 = ws4[k * 34 + cg * 2 + 1];
                wb[2] = pk2(w1.x, w1.y);
                wb[3] = pk2(w1.z, w1.w);
            }
            float4 ya = ys4[k * 64 + rot];
            float4 yb = ys4[k * 64 + 32 + rot];
            float yv[8] = {ya.x, ya.y, ya.z, ya.w, yb.x, yb.y, yb.z, yb.w};
            #pragma unroll
            for (int j = 0; j < 8; ++j) {
                unsigned long long a = pk2(yv[j], yv[j]);
                #pragma unroll
                for (int cj = 0; cj < NCJ; ++cj)
                    acc[j][cj] = fma2(a, wb[cj], acc[j][cj]);
            }
        }
    }
}

__global__ void __launch_bounds__(NTHREADS, 1)
ib_kernel(const float* __restrict__ x,
          const float* __restrict__ chi,
          const float* __restrict__ W,
          const float* __restrict__ b,
          float* __restrict__ out_a1,
          float* __restrict__ out_chi,
          int n)
{
    extern __shared__ float smem[];
    float* ws = smem;                  // [136][136]
    float* ys = ws + WS_FLOATS;        // [136][256] rotated layout
    float* bs = ys + YS_FLOATS;        // [136]

    const int tid  = threadIdx.x;
    const int row0 = blockIdx.x * ROWS;

    // ---- stage W (zero-padded 132x132 -> 136x136) ----
    for (int i = tid; i < KP * 34; i += NTHREADS) {
        int kk = i / 34;
        int cp = i - kk * 34;
        float4 v = make_float4(0.f, 0.f, 0.f, 0.f);
        if (kk < CDIM && cp < 33)
            v = *reinterpret_cast<const float4*>(W + kk * CDIM + cp * 4);
        *reinterpret_cast<float4*>(ws + kk * CP + cp * 4) = v;
    }

    // ---- stage bias (zero-padded) ----
    if (tid < 34) {
        float4 v = make_float4(0.f, 0.f, 0.f, 0.f);
        if (tid < 33) v = *reinterpret_cast<const float4*>(b + tid * 4);
        *reinterpret_cast<float4*>(bs + tid * 4) = v;
    }

    // ---- stage x transposed into ys (rotated layout) ----
    for (int i = tid; i < ROWS * 32; i += NTHREADS) {
        int r  = i >> 5;
        int kq = i & 31;
        float4 v = make_float4(0.f, 0.f, 0.f, 0.f);
        if (row0 + r < n)
            v = *reinterpret_cast<const float4*>(x + (size_t)(row0 + r) * FDIM + kq * 4);
        int g = r >> 3, j = r & 7;
        int base = (j >> 2) * 128 + (((g + kq) & 31) << 2) + (j & 3);
        ys[(4 * kq + 0) * ROWS + base] = v.x;
        ys[(4 * kq + 1) * ROWS + base] = v.y;
        ys[(4 * kq + 2) * ROWS + base] = v.z;
        ys[(4 * kq + 3) * ROWS + base] = v.w;
    }

    // ---- d_chi into ys rows 128..131; zeros 132..135 ----
    if (tid < ROWS) {
        int r = tid;
        float c[16];
        #pragma unroll
        for (int q = 0; q < 4; ++q) {
            float4 v = make_float4(0.f, 0.f, 0.f, 0.f);
            if (row0 + r < n)
                v = *reinterpret_cast<const float4*>(chi + (size_t)(row0 + r) * 16 + q * 4);
            c[q * 4 + 0] = v.x; c[q * 4 + 1] = v.y;
            c[q * 4 + 2] = v.z; c[q * 4 + 3] = v.w;
        }
        float s0 = c[0] * c[0];
        float s1 = c[1]*c[1] + c[2]*c[2] + c[3]*c[3];
        float s2 = 0.f, s3 = 0.f;
        #pragma unroll
        for (int m = 4; m < 9; ++m)  s2 += c[m] * c[m];
        #pragma unroll
        for (int m = 9; m < 16; ++m) s3 += c[m] * c[m];

        int g = r >> 3, j = r & 7;
        int half = (j >> 2) * 128, jj = j & 3;
        // k = 128..131 -> q = 32 -> (g+32)&31 = g
        int p32 = half + (g << 2) + jj;
        ys[(128) * ROWS + p32] = s0;
        ys[(129) * ROWS + p32] = s1;
        ys[(130) * ROWS + p32] = s2;
        ys[(131) * ROWS + p32] = s3;
        // k = 132..135 -> q = 33 -> (g+33)&31 = (g+1)&31
        int p33 = half + (((g + 1) & 31) << 2) + jj;
        ys[(132) * ROWS + p33] = 0.f;
        ys[(133) * ROWS + p33] = 0.f;
        ys[(134) * ROWS + p33] = 0.f;
        ys[(135) * ROWS + p33] = 0.f;
    }
    __syncthreads();

    // ---- thread mapping ----
    const int wid  = tid >> 5;
    const int lane = tid & 31;
    int g, cg;
    if (wid < 16) { g = 2 * wid + (lane >> 4); cg = lane & 15; }
    else          { g = lane;                  cg = 16; }

    unsigned long long acc[8][4];
    #pragma unroll
    for (int j = 0; j < 8; ++j)
        #pragma unroll
        for (int cj = 0; cj < 4; ++cj) acc[j][cj] = 0ull;

    if (wid < 16) mainloop<4>(ws, ys, g, cg, acc);
    else          mainloop<2>(ws, ys, g, cg, acc);

    // ---- epilogue ----
    if (cg < 16) {
        float4 bb0 = reinterpret_cast<const float4*>(bs)[cg * 2];
        float4 bb1 = reinterpret_cast<const float4*>(bs)[cg * 2 + 1];
        #pragma unroll
        for (int j = 0; j < 8; ++j) {
            int row = row0 + 8 * g + j;
            if (row < n) {
                float2 p0 = upk2(acc[j][0]);
                float2 p1 = upk2(acc[j][1]);
                float2 p2 = upk2(acc[j][2]);
                float2 p3 = upk2(acc[j][3]);
                float4 lo = make_float4(p0.x + bb0.x, p0.y + bb0.y,
                                        p1.x + bb0.z, p1.y + bb0.w);
                float4 hi = make_float4(p2.x + bb1.x, p2.y + bb1.y,
                                        p3.x + bb1.z, p3.y + bb1.w);
                float* dst = out_a1 + (size_t)row * FDIM + cg * 8;
                *reinterpret_cast<float4*>(dst)     = lo;
                *reinterpret_cast<float4*>(dst + 4) = hi;
            }
        }
    } else {
        // cols 128..131 -> b1[0..3]; chi_out[m] = b1[SEG[m]] * chi[m]
        float4 bb = reinterpret_cast<const float4*>(bs)[32];
        #pragma unroll
        for (int j = 0; j < 8; ++j) {
            int row = row0 + 8 * g + j;
            if (row < n) {
                float2 p0 = upk2(acc[j][0]);
                float2 p1 = upk2(acc[j][1]);
                float h0 = p0.x + bb.x;
                float h1 = p0.y + bb.y;
                float h2 = p1.x + bb.z;
                float h3 = p1.y + bb.w;
                const float* crow = chi + (size_t)row * 16;
                float c[16];
                #pragma unroll
                for (int q = 0; q < 4; ++q) {
                    float4 v = *reinterpret_cast<const float4*>(crow + q * 4);
                    c[q*4+0] = v.x; c[q*4+1] = v.y; c[q*4+2] = v.z; c[q*4+3] = v.w;
                }
                float o[16];
                o[0] = h0 * c[0];
                #pragma unroll
                for (int m = 1; m < 4; ++m)  o[m] = h1 * c[m];
                #pragma unroll
                for (int m = 4; m < 9; ++m)  o[m] = h2 * c[m];
                #pragma unroll
                for (int m = 9; m < 16; ++m) o[m] = h3 * c[m];
                float* dst = out_chi + (size_t)row * 16;
                #pragma unroll
                for (int q = 0; q < 4; ++q)
                    *reinterpret_cast<float4*>(dst + q * 4) =
                        make_float4(o[q*4], o[q*4+1], o[q*4+2], o[q*4+3]);
            }
        }
    }
}

extern "C" void kernel_launch(void* const* d_in, const int* in_sizes, int n_in,
                              void* d_out, int out_size)
{
    // Identify inputs by size (expected order: x, chi, point_mask, W, b)
    int ix = 0, ichi = 1, iW = 3, ib = 4;
    long long maxsz = -1;
    for (int i = 0; i < n_in; ++i)
        if ((long long)in_sizes[i] > maxsz) { maxsz = in_sizes[i]; ix = i; }
    long long n = maxsz / FDIM;
    for (int i = 0; i < n_in; ++i) {
        long long s = in_sizes[i];
        if (i == ix) continue;
        if (s == CDIM * CDIM) iW = i;
        else if (s == CDIM)   ib = i;
        else if (s == 16 * n) ichi = i;
    }

    const float* x   = (const float*)d_in[ix];
    const float* chi = (const float*)d_in[ichi];
    const float* W   = (const float*)d_in[iW];
    const float* b   = (const float*)d_in[ib];

    float* out_a1  = (float*)d_out;
    float* out_chi = out_a1 + (size_t)n * FDIM;

    cudaFuncSetAttribute(ib_kernel, cudaFuncAttributeMaxDynamicSharedMemorySize,
                         SMEM_BYTES);

    int grid = (int)((n + ROWS - 1) / ROWS);
    ib_kernel<<<grid, NTHREADS, SMEM_BYTES>>>(x, chi, W, b, out_a1, out_chi, (int)n);
}

// round 3
// speedup vs baseline: 1.2831x; 1.0123x over previous
#include <cuda_runtime.h>

// InteractionBlock: n=1e6, F=128, NL=4, M_TOT=16, C=F+NL=132
//   d_chi[i,l] = sum_{m:SEG[m]=l} chi[i,m]^2
//   y = [x, d_chi]  (132)
//   h = y @ W + b   (W: 132x132 row-major)
//   a1 = h[:, :128]; chi_out[:, m] = h[:, 128+SEG[m]] * chi[:, m]
// Output: [a1 (n*128) | chi_out (n*16)] float32

#define FDIM 128
#define CDIM 132
#define KP   136
#define CP   136
#define ROWS 256
#define NTHREADS 544   // 17 warps

// smem: ws[136][136] + ys[136][256] + bs[136]
#define WS_FLOATS  (KP * CP)        // 18496
#define YS_FLOATS  (KP * ROWS)      // 34816
#define BS_FLOATS  (CP)             // 136
#define SMEM_FLOATS (WS_FLOATS + YS_FLOATS + BS_FLOATS)
#define SMEM_BYTES (SMEM_FLOATS * 4)

__device__ __forceinline__ unsigned long long pk2(float lo, float hi) {
    unsigned long long r;
    asm("mov.b64 %0, {%1, %2};" : "=l"(r) : "f"(lo), "f"(hi));
    return r;
}
__device__ __forceinline__ unsigned long long fma2(unsigned long long a,
                                                   unsigned long long b,
                                                   unsigned long long c) {
    unsigned long long d;
    asm("fma.rn.f32x2 %0, %1, %2, %3;" : "=l"(d) : "l"(a), "l"(b), "l"(c));
    return d;
}
__device__ __forceinline__ float2 upk2(unsigned long long v) {
    float2 f;
    asm("mov.b64 {%0, %1}, %2;" : "=f"(f.x), "=f"(f.y) : "l"(v));
    return f;
}

// ys layout: row r (g=r>>3, j=r&7, half=j>>2, jj=j&3), k (q=k>>2):
//   ys[k*256 + half*128 + ((g+q)&31)*4 + jj]
// Mainloop read (lane=g): float4 at k*64 + half*32 + ((g+q)&31)  (conflict-free)

template<int NCJ>
__device__ __forceinline__ void mainloop(const float* ws, const float* ys,
                                         int g, int cg,
                                         unsigned long long acc[8][4])
{
    const float4* ws4 = reinterpret_cast<const float4*>(ws);
    const float4* ys4 = reinterpret_cast<const float4*>(ys);
    #pragma unroll 2
    for (int kq = 0; kq < 34; ++kq) {
        const int rot = (g + kq) & 31;
        #pragma unroll
        for (int c = 0; c < 4; ++c) {
            const int k = 4 * kq + c;
            unsigned long long wb[4];
            float4 w0 = ws4[k * 34 + cg * 2];
            wb[0] = pk2(w0.x, w0.y);
            wb[1] = pk2(w0.z, w0.w);
            if (NCJ == 4) {
                float4 w1 = ws4[k * 34 + cg * 2 + 1];
                wb[2] = pk2(w1.x, w1.y);
                wb[3] = pk2(w1.z, w1.w);
            }
            float4 ya = ys4[k * 64 + rot];
            float4 yb = ys4[k * 64 + 32 + rot];
            float yv[8] = {ya.x, ya.y, ya.z, ya.w, yb.x, yb.y, yb.z, yb.w};
            #pragma unroll
            for (int j = 0; j < 8; ++j) {
                unsigned long long a = pk2(yv[j], yv[j]);
                #pragma unroll
                for (int cj = 0; cj < NCJ; ++cj)
                    acc[j][cj] = fma2(a, wb[cj], acc[j][cj]);
            }
        }
    }
}

__global__ void __launch_bounds__(NTHREADS, 1)
ib_kernel(const float* __restrict__ x,
          const float* __restrict__ chi,
          const float* __restrict__ W,
          const float* __restrict__ b,
          float* __restrict__ out_a1,
          float* __restrict__ out_chi,
          int n)
{
    extern __shared__ float smem[];
    float* ws = smem;                  // [136][136]
    float* ys = ws + WS_FLOATS;        // [136][256] rotated layout
    float* bs = ys + YS_FLOATS;        // [136]

    const int tid  = threadIdx.x;
    const int row0 = blockIdx.x * ROWS;

    // ---- stage W (zero-padded 132x132 -> 136x136) ----
    for (int i = tid; i < KP * 34; i += NTHREADS) {
        int kk = i / 34;
        int cp = i - kk * 34;
        float4 v = make_float4(0.f, 0.f, 0.f, 0.f);
        if (kk < CDIM && cp < 33)
            v = *reinterpret_cast<const float4*>(W + kk * CDIM + cp * 4);
        *reinterpret_cast<float4*>(ws + kk * CP + cp * 4) = v;
    }

    // ---- stage bias (zero-padded) ----
    if (tid < 34) {
        float4 v = make_float4(0.f, 0.f, 0.f, 0.f);
        if (tid < 33) v = *reinterpret_cast<const float4*>(b + tid * 4);
        *reinterpret_cast<float4*>(bs + tid * 4) = v;
    }

    // ---- stage x transposed into ys (rotated layout) ----
    for (int i = tid; i < ROWS * 32; i += NTHREADS) {
        int r  = i >> 5;
        int kq = i & 31;
        float4 v = make_float4(0.f, 0.f, 0.f, 0.f);
        if (row0 + r < n)
            v = *reinterpret_cast<const float4*>(x + (size_t)(row0 + r) * FDIM + kq * 4);
        int g = r >> 3, j = r & 7;
        int base = (j >> 2) * 128 + (((g + kq) & 31) << 2) + (j & 3);
        ys[(4 * kq + 0) * ROWS + base] = v.x;
        ys[(4 * kq + 1) * ROWS + base] = v.y;
        ys[(4 * kq + 2) * ROWS + base] = v.z;
        ys[(4 * kq + 3) * ROWS + base] = v.w;
    }

    // ---- d_chi into ys rows 128..131; zeros 132..135 ----
    if (tid < ROWS) {
        int r = tid;
        float c[16];
        #pragma unroll
        for (int q = 0; q < 4; ++q) {
            float4 v = make_float4(0.f, 0.f, 0.f, 0.f);
            if (row0 + r < n)
                v = *reinterpret_cast<const float4*>(chi + (size_t)(row0 + r) * 16 + q * 4);
            c[q * 4 + 0] = v.x; c[q * 4 + 1] = v.y;
            c[q * 4 + 2] = v.z; c[q * 4 + 3] = v.w;
        }
        float s0 = c[0] * c[0];
        float s1 = c[1]*c[1] + c[2]*c[2] + c[3]*c[3];
        float s2 = 0.f, s3 = 0.f;
        #pragma unroll
        for (int m = 4; m < 9; ++m)  s2 += c[m] * c[m];
        #pragma unroll
        for (int m = 9; m < 16; ++m) s3 += c[m] * c[m];

        int g = r >> 3, j = r & 7;
        int half = (j >> 2) * 128, jj = j & 3;
        // k = 128..131 -> q = 32 -> (g+32)&31 = g
        int p32 = half + (g << 2) + jj;
        ys[(128) * ROWS + p32] = s0;
        ys[(129) * ROWS + p32] = s1;
        ys[(130) * ROWS + p32] = s2;
        ys[(131) * ROWS + p32] = s3;
        // k = 132..135 -> q = 33 -> (g+33)&31 = (g+1)&31
        int p33 = half + (((g + 1) & 31) << 2) + jj;
        ys[(132) * ROWS + p33] = 0.f;
        ys[(133) * ROWS + p33] = 0.f;
        ys[(134) * ROWS + p33] = 0.f;
        ys[(135) * ROWS + p33] = 0.f;
    }
    __syncthreads();

    // ---- thread mapping ----
    const int wid  = tid >> 5;
    const int lane = tid & 31;
    int g, cg;
    if (wid < 16) { g = 2 * wid + (lane >> 4); cg = lane & 15; }
    else          { g = lane;                  cg = 16; }

    unsigned long long acc[8][4];
    #pragma unroll
    for (int j = 0; j < 8; ++j)
        #pragma unroll
        for (int cj = 0; cj < 4; ++cj) acc[j][cj] = 0ull;

    if (wid < 16) mainloop<4>(ws, ys, g, cg, acc);
    else          mainloop<2>(ws, ys, g, cg, acc);

    // ---- epilogue ----
    if (cg < 16) {
        float4 bb0 = reinterpret_cast<const float4*>(bs)[cg * 2];
        float4 bb1 = reinterpret_cast<const float4*>(bs)[cg * 2 + 1];
        #pragma unroll
        for (int j = 0; j < 8; ++j) {
            int row = row0 + 8 * g + j;
            if (row < n) {
                float2 p0 = upk2(acc[j][0]);
                float2 p1 = upk2(acc[j][1]);
                float2 p2 = upk2(acc[j][2]);
                float2 p3 = upk2(acc[j][3]);
                float4 lo = make_float4(p0.x + bb0.x, p0.y + bb0.y,
                                        p1.x + bb0.z, p1.y + bb0.w);
                float4 hi = make_float4(p2.x + bb1.x, p2.y + bb1.y,
                                        p3.x + bb1.z, p3.y + bb1.w);
                float* dst = out_a1 + (size_t)row * FDIM + cg * 8;
                *reinterpret_cast<float4*>(dst)     = lo;
                *reinterpret_cast<float4*>(dst + 4) = hi;
            }
        }
    } else {
        // cols 128..131 -> b1[0..3]; chi_out[m] = b1[SEG[m]] * chi[m]
        float4 bb = reinterpret_cast<const float4*>(bs)[32];
        #pragma unroll
        for (int j = 0; j < 8; ++j) {
            int row = row0 + 8 * g + j;
            if (row < n) {
                float2 p0 = upk2(acc[j][0]);
                float2 p1 = upk2(acc[j][1]);
                float h0 = p0.x + bb.x;
                float h1 = p0.y + bb.y;
                float h2 = p1.x + bb.z;
                float h3 = p1.y + bb.w;
                const float* crow = chi + (size_t)row * 16;
                float c[16];
                #pragma unroll
                for (int q = 0; q < 4; ++q) {
                    float4 v = *reinterpret_cast<const float4*>(crow + q * 4);
                    c[q*4+0] = v.x; c[q*4+1] = v.y; c[q*4+2] = v.z; c[q*4+3] = v.w;
                }
                float o[16];
                o[0] = h0 * c[0];
                #pragma unroll
                for (int m = 1; m < 4; ++m)  o[m] = h1 * c[m];
                #pragma unroll
                for (int m = 4; m < 9; ++m)  o[m] = h2 * c[m];
                #pragma unroll
                for (int m = 9; m < 16; ++m) o[m] = h3 * c[m];
                float* dst = out_chi + (size_t)row * 16;
                #pragma unroll
                for (int q = 0; q < 4; ++q)
                    *reinterpret_cast<float4*>(dst + q * 4) =
                        make_float4(o[q*4], o[q*4+1], o[q*4+2], o[q*4+3]);
            }
        }
    }
}

extern "C" void kernel_launch(void* const* d_in, const int* in_sizes, int n_in,
                              void* d_out, int out_size)
{
    // Identify inputs by size (expected order: x, chi, point_mask, W, b)
    int ix = 0, ichi = 1, iW = 3, ib = 4;
    long long maxsz = -1;
    for (int i = 0; i < n_in; ++i)
        if ((long long)in_sizes[i] > maxsz) { maxsz = in_sizes[i]; ix = i; }
    long long n = maxsz / FDIM;
    for (int i = 0; i < n_in; ++i) {
        long long s = in_sizes[i];
        if (i == ix) continue;
        if (s == CDIM * CDIM) iW = i;
        else if (s == CDIM)   ib = i;
        else if (s == 16 * n) ichi = i;
    }

    const float* x   = (const float*)d_in[ix];
    const float* chi = (const float*)d_in[ichi];
    const float* W   = (const float*)d_in[iW];
    const float* b   = (const float*)d_in[ib];

    float* out_a1  = (float*)d_out;
    float* out_chi = out_a1 + (size_t)n * FDIM;

    cudaFuncSetAttribute(ib_kernel, cudaFuncAttributeMaxDynamicSharedMemorySize,
                         SMEM_BYTES);

    int grid = (int)((n + ROWS - 1) / ROWS);
    ib_kernel<<<grid, NTHREADS, SMEM_BYTES>>>(x, chi, W, b, out_a1, out_chi, (int)n);
}

// round 7
// speedup vs baseline: 2.7489x; 2.1424x over previous
#include <cuda_runtime.h>
#include <cuda_bf16.h>
#include <cstdint>

#define FDIM 128
#define CDIM 132
#define KBE  136          // padded K in bf16 elements
#define RSTR 272          // bytes per smem row (136 bf16)
#define TILE 64
#define NTHR 128

// smem byte offsets
#define SM_BS   0                          // bias: 136 floats
#define SM_B1S  1024                       // b1 buffer: 64 x 4 floats
#define SM_YH   2048
#define SM_YL   (SM_YH + TILE * RSTR)      // 19456
#define SM_WH   (SM_YL + TILE * RSTR)      // 36864
#define SM_WL   (SM_WH + KBE * RSTR)       // 73856
#define SMEM_BYTES (SM_WL + KBE * RSTR)    // 110848

static __device__ __forceinline__ uint32_t smem_u32(const void* p) {
    uint32_t a;
    asm("{ .reg .u64 t; cvta.to.shared.u64 t, %1; cvt.u32.u64 %0, t; }" : "=r"(a) : "l"(p));
    return a;
}
static __device__ __forceinline__ void split(float v, unsigned short& h, unsigned short& l) {
    __nv_bfloat16 hb = __float2bfloat16(v);
    float r = v - __bfloat162float(hb);
    __nv_bfloat16 lb = __float2bfloat16(r);
    h = __bfloat16_as_ushort(hb);
    l = __bfloat16_as_ushort(lb);
}
static __device__ __forceinline__ void sp2(float a, float b, uint32_t& h, uint32_t& l) {
    unsigned short ha, la, hb, lb;
    split(a, ha, la); split(b, hb, lb);
    h = (uint32_t)ha | ((uint32_t)hb << 16);
    l = (uint32_t)la | ((uint32_t)lb << 16);
}

static __device__ __forceinline__ void ldsm4(uint32_t a, uint32_t* r) {
    asm volatile("ldmatrix.sync.aligned.m8n8.x4.shared.b16 {%0,%1,%2,%3}, [%4];"
        : "=r"(r[0]), "=r"(r[1]), "=r"(r[2]), "=r"(r[3]) : "r"(a));
}
static __device__ __forceinline__ void ldsm2(uint32_t a, uint32_t* r) {
    asm volatile("ldmatrix.sync.aligned.m8n8.x2.shared.b16 {%0,%1}, [%2];"
        : "=r"(r[0]), "=r"(r[1]) : "r"(a));
}
static __device__ __forceinline__ void ldsm1(uint32_t a, uint32_t* r) {
    asm volatile("ldmatrix.sync.aligned.m8n8.x1.shared.b16 {%0}, [%1];"
        : "=r"(r[0]) : "r"(a));
}
static __device__ __forceinline__ void mma16(float* c, const uint32_t* A, const uint32_t* B) {
    asm volatile("mma.sync.aligned.m16n8k16.row.col.f32.bf16.bf16.f32 "
        "{%0,%1,%2,%3}, {%4,%5,%6,%7}, {%8,%9}, {%0,%1,%2,%3};"
        : "+f"(c[0]), "+f"(c[1]), "+f"(c[2]), "+f"(c[3])
        : "r"(A[0]), "r"(A[1]), "r"(A[2]), "r"(A[3]), "r"(B[0]), "r"(B[1]));
}
static __device__ __forceinline__ void mma8(float* c, const uint32_t* A, uint32_t B) {
    asm volatile("mma.sync.aligned.m16n8k8.row.col.f32.bf16.bf16.f32 "
        "{%0,%1,%2,%3}, {%4,%5}, {%6}, {%0,%1,%2,%3};"
        : "+f"(c[0]), "+f"(c[1]), "+f"(c[2]), "+f"(c[3])
        : "r"(A[0]), "r"(A[1]), "r"(B));
}

struct Offs {
    uint32_t aoff;       // A ldmatrix offset (x4 tiles, f adds 4352)
    uint32_t bpo[4];     // B x4 pair offsets (k16)
    uint32_t b16s;       // B x2 single-group offset pattern (k16, group 8)
    uint32_t b8po[4];    // B x2 pair offsets (k8 step)
    uint32_t b8s;        // B x1 single-group offset (k8, group 8)
};

template<int NG>
static __device__ __forceinline__ void mma_pass(uint32_t ab, uint32_t bb,
                                                const Offs& o, float (*acc)[4])
{
    #pragma unroll
    for (int s = 0; s < 8; ++s) {
        const uint32_t kb = (uint32_t)s * 32;
        uint32_t A0[4], A1[4];
        ldsm4(ab + o.aoff + kb, A0);
        ldsm4(ab + o.aoff + 4352 + kb, A1);
        uint32_t B[NG][2];
        #pragma unroll
        for (int p = 0; p < NG / 2; ++p) {
            uint32_t r[4];
            ldsm4(bb + o.bpo[p] + kb, r);
            B[2*p][0] = r[0]; B[2*p][1] = r[1];
            B[2*p+1][0] = r[2]; B[2*p+1][1] = r[3];
        }
        if (NG & 1) ldsm2(bb + o.b16s + kb, B[NG-1]);
        #pragma unroll
        for (int g = 0; g < NG; ++g) {
            mma16(acc[g], A0, B[g]);
            mma16(acc[NG + g], A1, B[g]);
        }
    }
    // k8 tail: k = 128..135
    {
        uint32_t A0[2], A1[2];
        ldsm2(ab + o.aoff + 256, A0);
        ldsm2(ab + o.aoff + 4352 + 256, A1);
        uint32_t B8[NG];
        #pragma unroll
        for (int p = 0; p < NG / 2; ++p) {
            uint32_t r[2];
            ldsm2(bb + o.b8po[p], r);
            B8[2*p] = r[0]; B8[2*p+1] = r[1];
        }
        if (NG & 1) { uint32_t r[1]; ldsm1(bb + o.b8s, r); B8[NG-1] = r[0]; }
        #pragma unroll
        for (int g = 0; g < NG; ++g) {
            mma8(acc[g], A0, B8[g]);
            mma8(acc[NG + g], A1, B8[g]);
        }
    }
}

template<int CW>
static __device__ __forceinline__ void compute_tile(
    uint32_t yhb, uint32_t ylb, uint32_t whb, uint32_t wlb,
    const Offs& o, const float* bs, float* b1s,
    float* __restrict__ a1, long long row0, long long n,
    int mrow, int qr, int qc)
{
    constexpr int NG = CW ? 8 : 9;
    constexpr int G0 = CW ? 9 : 0;

    float acc[2 * NG][4];
    #pragma unroll
    for (int i = 0; i < 2 * NG; ++i)
        #pragma unroll
        for (int j = 0; j < 4; ++j) acc[i][j] = 0.f;

    mma_pass<NG>(yhb, whb, o, acc);   // hi * hi
    mma_pass<NG>(yhb, wlb, o, acc);   // hi * lo
    mma_pass<NG>(ylb, whb, o, acc);   // lo * hi

    // epilogue
    #pragma unroll
    for (int f = 0; f < 2; ++f) {
        #pragma unroll
        for (int g = 0; g < NG; ++g) {
            const int ga = G0 + g;
            const float* ac = acc[f * NG + g];
            const int colg = ga * 8 + qc * 2;
            if (ga < 16) {
                float bx = bs[colg], by = bs[colg + 1];
                long long r1 = row0 + mrow + f * 16 + qr;
                if (r1 < n)
                    *(float2*)(a1 + r1 * FDIM + colg) = make_float2(ac[0] + bx, ac[1] + by);
                if (r1 + 8 < n)
                    *(float2*)(a1 + (r1 + 8) * FDIM + colg) = make_float2(ac[2] + bx, ac[3] + by);
            } else if (ga == 16) {
                if (qc < 2) {
                    int l = qc * 2;
                    float bx = bs[FDIM + l], by = bs[FDIM + l + 1];
                    int rl = mrow + f * 16 + qr;
                    b1s[rl * 4 + l]       = ac[0] + bx;
                    b1s[rl * 4 + l + 1]   = ac[1] + by;
                    b1s[(rl + 8) * 4 + l]     = ac[2] + bx;
                    b1s[(rl + 8) * 4 + l + 1] = ac[3] + by;
                }
            }
        }
    }
}

__global__ void __launch_bounds__(NTHR, 2)
ib_mma(const float* __restrict__ x, const float* __restrict__ chi,
       const float* __restrict__ W, const float* __restrict__ b,
       float* __restrict__ a1, float* __restrict__ co,
       long long n, long long T)
{
    extern __shared__ char sm[];
    float* bs  = (float*)(sm + SM_BS);
    float* b1s = (float*)(sm + SM_B1S);
    unsigned short* whp = (unsigned short*)(sm + SM_WH);
    unsigned short* wlp = (unsigned short*)(sm + SM_WL);

    const int tid = threadIdx.x, wid = tid >> 5, lane = tid & 31;
    const uint32_t smb = smem_u32(sm);
    const uint32_t yhb = smb + SM_YH, ylb = smb + SM_YL;
    const uint32_t whb = smb + SM_WH, wlb = smb + SM_WL;

    // ---- stage W^T (hi/lo bf16) + bias, once ----
    for (int i = tid; i < KBE * KBE; i += NTHR) {
        int nn = i % KBE, kk = i / KBE;
        float w = (nn < CDIM && kk < CDIM) ? W[kk * CDIM + nn] : 0.f;
        unsigned short h, l;
        split(w, h, l);
        whp[nn * KBE + kk] = h;
        wlp[nn * KBE + kk] = l;
    }
    for (int i = tid; i < KBE; i += NTHR) bs[i] = (i < CDIM) ? b[i] : 0.f;
    __syncthreads();

    // ---- per-warp ldmatrix offsets ----
    const int mrow = (wid & 1) * 32;
    const int cw   = wid >> 1;               // 0: groups 0..8, 1: groups 9..16
    const int j3 = lane >> 3, rw = lane & 7;
    const int qr = lane >> 2, qc = lane & 3;
    const int g0 = cw ? 9 : 0;

    Offs o;
    o.aoff = (uint32_t)((mrow + ((j3 & 1) << 3) + rw) * RSTR + ((j3 >> 1) << 4));
    #pragma unroll
    for (int p = 0; p < 4; ++p) {
        int g = g0 + 2 * p;
        o.bpo[p]  = (uint32_t)((g * 8 + ((j3 >> 1) << 3) + rw) * RSTR + ((j3 & 1) << 4));
        o.b8po[p] = (uint32_t)((g * 8 + ((j3 & 1) << 3) + rw) * RSTR + 256);
    }
    o.b16s = (uint32_t)((64 + rw) * RSTR + ((j3 & 1) << 4));
    o.b8s  = (uint32_t)((64 + rw) * RSTR + 256);

    // staging / chi mapping
    const int r2 = tid >> 1, hh = tid & 1;
    const int grid = gridDim.x;

    for (long long t = blockIdx.x; t < T; t += grid) {
        const long long row0 = t * TILE;
        const long long row = row0 + r2;
        const bool ok = row < n;

        // ---- stage y (x part) ----
        {
            const float* xp = x + row * FDIM + hh * 64;
            unsigned short* dsth = (unsigned short*)(sm + SM_YH) + r2 * KBE + hh * 64;
            unsigned short* dstl = (unsigned short*)(sm + SM_YL) + r2 * KBE + hh * 64;
            #pragma unroll
            for (int c = 0; c < 8; ++c) {
                float4 va = ok ? *(const float4*)(xp + c * 8)     : make_float4(0, 0, 0, 0);
                float4 vb = ok ? *(const float4*)(xp + c * 8 + 4) : make_float4(0, 0, 0, 0);
                uint4 hv, lv;
                sp2(va.x, va.y, hv.x, lv.x);
                sp2(va.z, va.w, hv.y, lv.y);
                sp2(vb.x, vb.y, hv.z, lv.z);
                sp2(vb.z, vb.w, hv.w, lv.w);
                *(uint4*)(dsth + c * 8) = hv;
                *(uint4*)(dstl + c * 8) = lv;
            }
        }

        // ---- chi + d_chi ----
        float cvx[8];
        {
            const float4* cp = (const float4*)(chi + row * 16 + hh * 8);
            float4 ca = ok ? cp[0] : make_float4(0, 0, 0, 0);
            float4 cb = ok ? cp[1] : make_float4(0, 0, 0, 0);
            cvx[0] = ca.x; cvx[1] = ca.y; cvx[2] = ca.z; cvx[3] = ca.w;
            cvx[4] = cb.x; cvx[5] = cb.y; cvx[6] = cb.z; cvx[7] = cb.w;

            float qa = ca.x * ca.x;
            float qb = ca.y * ca.y + ca.z * ca.z + ca.w * ca.w;
            float qc2 = cb.x * cb.x + cb.y * cb.y + cb.z * cb.z + cb.w * cb.w;
            float s0, s1, s2, s3;
            if (hh == 0) { s0 = qa;  s1 = qb;  s2 = qc2; s3 = 0.f; }
            else         { s0 = 0.f; s1 = 0.f; s2 = qa;  s3 = qb + qc2; }
            s0 += __shfl_xor_sync(0xFFFFFFFFu, s0, 1);
            s1 += __shfl_xor_sync(0xFFFFFFFFu, s1, 1);
            s2 += __shfl_xor_sync(0xFFFFFFFFu, s2, 1);
            s3 += __shfl_xor_sync(0xFFFFFFFFu, s3, 1);

            uint32_t h0, l0, h1, l1;
            sp2(s0, s1, h0, l0);
            sp2(s2, s3, h1, l1);
            if (hh == 0)
                *(uint4*)(sm + SM_YH + r2 * RSTR + 256) = make_uint4(h0, h1, 0u, 0u);
            else
                *(uint4*)(sm + SM_YL + r2 * RSTR + 256) = make_uint4(l0, l1, 0u, 0u);
        }
        __syncthreads();

        // ---- MMA + a1/b1 epilogue ----
        if (cw == 0)
            compute_tile<0>(yhb, ylb, whb, wlb, o, bs, b1s, a1, row0, n, mrow, qr, qc);
        else
            compute_tile<1>(yhb, ylb, whb, wlb, o, bs, b1s, a1, row0, n, mrow, qr, qc);
        __syncthreads();

        // ---- chi_out ----
        if (ok) {
            float4 bv = ((const float4*)b1s)[r2];
            float o8[8];
            if (hh == 0) {
                o8[0] = bv.x * cvx[0];
                o8[1] = bv.y * cvx[1]; o8[2] = bv.y * cvx[2]; o8[3] = bv.y * cvx[3];
                o8[4] = bv.z * cvx[4]; o8[5] = bv.z * cvx[5];
                o8[6] = bv.z * cvx[6]; o8[7] = bv.z * cvx[7];
            } else {
                o8[0] = bv.z * cvx[0];
                #pragma unroll
                for (int m = 1; m < 8; ++m) o8[m] = bv.w * cvx[m];
            }
            float4* dst = (float4*)(co + row * 16 + hh * 8);
            dst[0] = make_float4(o8[0], o8[1], o8[2], o8[3]);
            dst[1] = make_float4(o8[4], o8[5], o8[6], o8[7]);
        }
        __syncthreads();
    }
}

extern "C" void kernel_launch(void* const* d_in, const int* in_sizes, int n_in,
                              void* d_out, int out_size)
{
    int ix = 0, ichi = 1, iW = 3, ib_ = 4;
    long long maxsz = -1;
    for (int i = 0; i < n_in; ++i)
        if ((long long)in_sizes[i] > maxsz) { maxsz = in_sizes[i]; ix = i; }
    long long n = maxsz / FDIM;
    for (int i = 0; i < n_in; ++i) {
        long long s = in_sizes[i];
        if (i == ix) continue;
        if (s == CDIM * CDIM) iW = i;
        else if (s == CDIM)   ib_ = i;
        else if (s == 16 * n) ichi = i;
    }
    const float* x   = (const float*)d_in[ix];
    const float* chi = (const float*)d_in[ichi];
    const float* W   = (const float*)d_in[iW];
    const float* b   = (const float*)d_in[ib_];
    float* a1 = (float*)d_out;
    float* co = a1 + (size_t)n * FDIM;

    long long T = (n + TILE - 1) / TILE;
    int sms = 148;
    cudaDeviceGetAttribute(&sms, cudaDevAttrMultiProcessorCount, 0);
    long long g = 2LL * sms;
    int grid = (int)(T < g ? T : g);

    cudaFuncSetAttribute(ib_mma, cudaFuncAttributeMaxDynamicSharedMemorySize, SMEM_BYTES);
    ib_mma<<<grid, NTHR, SMEM_BYTES>>>(x, chi, W, b, a1, co, n, T);
}

// round 8
// speedup vs baseline: 2.9329x; 1.0669x over previous
#include <cuda_runtime.h>
#include <cuda_bf16.h>
#include <cstdint>

#define FDIM 128
#define CDIM 132
#define KBE  136          // padded K in bf16 elements
#define RSTR 272          // bytes per smem row (136 bf16)
#define TILE 64
#define NTHR 128

// smem byte offsets
#define SM_BS   0                          // bias: 136 floats
#define SM_B1S  1024                       // b1 buffer: 64 x 4 floats
#define SM_YH   2048
#define SM_YL   (SM_YH + TILE * RSTR)      // 19456
#define SM_WH   (SM_YL + TILE * RSTR)      // 36864
#define SM_WL   (SM_WH + KBE * RSTR)       // 73856
#define SMEM_BYTES (SM_WL + KBE * RSTR)    // 110848

static __device__ __forceinline__ uint32_t smem_u32(const void* p) {
    uint32_t a;
    asm("{ .reg .u64 t; cvta.to.shared.u64 t, %1; cvt.u32.u64 %0, t; }" : "=r"(a) : "l"(p));
    return a;
}
static __device__ __forceinline__ void split(float v, unsigned short& h, unsigned short& l) {
    __nv_bfloat16 hb = __float2bfloat16(v);
    float r = v - __bfloat162float(hb);
    __nv_bfloat16 lb = __float2bfloat16(r);
    h = __bfloat16_as_ushort(hb);
    l = __bfloat16_as_ushort(lb);
}
static __device__ __forceinline__ void sp2(float a, float b, uint32_t& h, uint32_t& l) {
    unsigned short ha, la, hb, lb;
    split(a, ha, la); split(b, hb, lb);
    h = (uint32_t)ha | ((uint32_t)hb << 16);
    l = (uint32_t)la | ((uint32_t)lb << 16);
}

static __device__ __forceinline__ void ldsm4(uint32_t a, uint32_t* r) {
    asm volatile("ldmatrix.sync.aligned.m8n8.x4.shared.b16 {%0,%1,%2,%3}, [%4];"
        : "=r"(r[0]), "=r"(r[1]), "=r"(r[2]), "=r"(r[3]) : "r"(a));
}
static __device__ __forceinline__ void ldsm2(uint32_t a, uint32_t* r) {
    asm volatile("ldmatrix.sync.aligned.m8n8.x2.shared.b16 {%0,%1}, [%2];"
        : "=r"(r[0]), "=r"(r[1]) : "r"(a));
}
static __device__ __forceinline__ void ldsm1(uint32_t a, uint32_t* r) {
    asm volatile("ldmatrix.sync.aligned.m8n8.x1.shared.b16 {%0}, [%1];"
        : "=r"(r[0]) : "r"(a));
}
static __device__ __forceinline__ void mma16(float* c, const uint32_t* A, const uint32_t* B) {
    asm volatile("mma.sync.aligned.m16n8k16.row.col.f32.bf16.bf16.f32 "
        "{%0,%1,%2,%3}, {%4,%5,%6,%7}, {%8,%9}, {%0,%1,%2,%3};"
        : "+f"(c[0]), "+f"(c[1]), "+f"(c[2]), "+f"(c[3])
        : "r"(A[0]), "r"(A[1]), "r"(A[2]), "r"(A[3]), "r"(B[0]), "r"(B[1]));
}
static __device__ __forceinline__ void mma8(float* c, const uint32_t* A, uint32_t B) {
    asm volatile("mma.sync.aligned.m16n8k8.row.col.f32.bf16.bf16.f32 "
        "{%0,%1,%2,%3}, {%4,%5}, {%6}, {%0,%1,%2,%3};"
        : "+f"(c[0]), "+f"(c[1]), "+f"(c[2]), "+f"(c[3])
        : "r"(A[0]), "r"(A[1]), "r"(B));
}

struct Offs {
    uint32_t aoff;       // A ldmatrix offset (x4 tiles, second frag adds 4352)
    uint32_t bpo[4];     // B x4 pair offsets (k16)
    uint32_t b16s;       // B x2 single-group offset (k16, last group)
    uint32_t b8po[4];    // B x2 pair offsets (k8 tail)
    uint32_t b8s;        // B x1 single-group offset (k8 tail)
};

// Fused: one sweep over k, loading A_hi/A_lo/B_hi/B_lo fragments once and
// issuing all 3 products (hi*hi + hi*lo + lo*hi) against registers.
template<int NG>
static __device__ __forceinline__ void mma_fused(
    uint32_t yhb, uint32_t ylb, uint32_t whb, uint32_t wlb,
    const Offs& o, float (*acc)[4])
{
    #pragma unroll
    for (int s = 0; s < 8; ++s) {
        const uint32_t kb = (uint32_t)s * 32;
        uint32_t Ah0[4], Ah1[4], Al0[4], Al1[4];
        ldsm4(yhb + o.aoff + kb, Ah0);
        ldsm4(yhb + o.aoff + 4352 + kb, Ah1);
        ldsm4(ylb + o.aoff + kb, Al0);
        ldsm4(ylb + o.aoff + 4352 + kb, Al1);
        uint32_t Bh[NG][2], Bl[NG][2];
        #pragma unroll
        for (int p = 0; p < NG / 2; ++p) {
            uint32_t r[4];
            ldsm4(whb + o.bpo[p] + kb, r);
            Bh[2*p][0] = r[0]; Bh[2*p][1] = r[1];
            Bh[2*p+1][0] = r[2]; Bh[2*p+1][1] = r[3];
            ldsm4(wlb + o.bpo[p] + kb, r);
            Bl[2*p][0] = r[0]; Bl[2*p][1] = r[1];
            Bl[2*p+1][0] = r[2]; Bl[2*p+1][1] = r[3];
        }
        if (NG & 1) {
            ldsm2(whb + o.b16s + kb, Bh[NG-1]);
            ldsm2(wlb + o.b16s + kb, Bl[NG-1]);
        }
        #pragma unroll
        for (int g = 0; g < NG; ++g) {
            mma16(acc[g],      Ah0, Bh[g]);
            mma16(acc[NG + g], Ah1, Bh[g]);
            mma16(acc[g],      Ah0, Bl[g]);
            mma16(acc[NG + g], Ah1, Bl[g]);
            mma16(acc[g],      Al0, Bh[g]);
            mma16(acc[NG + g], Al1, Bh[g]);
        }
    }
    // k8 tail: k = 128..135
    {
        uint32_t Ah0[2], Ah1[2], Al0[2], Al1[2];
        ldsm2(yhb + o.aoff + 256, Ah0);
        ldsm2(yhb + o.aoff + 4352 + 256, Ah1);
        ldsm2(ylb + o.aoff + 256, Al0);
        ldsm2(ylb + o.aoff + 4352 + 256, Al1);
        uint32_t B8h[NG], B8l[NG];
        #pragma unroll
        for (int p = 0; p < NG / 2; ++p) {
            uint32_t r[2];
            ldsm2(whb + o.b8po[p], r);
            B8h[2*p] = r[0]; B8h[2*p+1] = r[1];
            ldsm2(wlb + o.b8po[p], r);
            B8l[2*p] = r[0]; B8l[2*p+1] = r[1];
        }
        if (NG & 1) {
            uint32_t r[1];
            ldsm1(whb + o.b8s, r); B8h[NG-1] = r[0];
            ldsm1(wlb + o.b8s, r); B8l[NG-1] = r[0];
        }
        #pragma unroll
        for (int g = 0; g < NG; ++g) {
            mma8(acc[g],      Ah0, B8h[g]);
            mma8(acc[NG + g], Ah1, B8h[g]);
            mma8(acc[g],      Ah0, B8l[g]);
            mma8(acc[NG + g], Ah1, B8l[g]);
            mma8(acc[g],      Al0, B8h[g]);
            mma8(acc[NG + g], Al1, B8h[g]);
        }
    }
}

template<int CW>
static __device__ __forceinline__ void compute_tile(
    uint32_t yhb, uint32_t ylb, uint32_t whb, uint32_t wlb,
    const Offs& o, const float* bs, float* b1s,
    float* __restrict__ a1, long long row0, long long n,
    int mrow, int qr, int qc)
{
    constexpr int NG = CW ? 8 : 9;
    constexpr int G0 = CW ? 9 : 0;

    float acc[2 * NG][4];
    #pragma unroll
    for (int i = 0; i < 2 * NG; ++i)
        #pragma unroll
        for (int j = 0; j < 4; ++j) acc[i][j] = 0.f;

    mma_fused<NG>(yhb, ylb, whb, wlb, o, acc);

    // epilogue
    #pragma unroll
    for (int f = 0; f < 2; ++f) {
        #pragma unroll
        for (int g = 0; g < NG; ++g) {
            const int ga = G0 + g;
            const float* ac = acc[f * NG + g];
            const int colg = ga * 8 + qc * 2;
            if (ga < 16) {
                float bx = bs[colg], by = bs[colg + 1];
                long long r1 = row0 + mrow + f * 16 + qr;
                if (r1 < n)
                    *(float2*)(a1 + r1 * FDIM + colg) = make_float2(ac[0] + bx, ac[1] + by);
                if (r1 + 8 < n)
                    *(float2*)(a1 + (r1 + 8) * FDIM + colg) = make_float2(ac[2] + bx, ac[3] + by);
            } else if (ga == 16) {
                if (qc < 2) {
                    int l = qc * 2;
                    float bx = bs[FDIM + l], by = bs[FDIM + l + 1];
                    int rl = mrow + f * 16 + qr;
                    b1s[rl * 4 + l]       = ac[0] + bx;
                    b1s[rl * 4 + l + 1]   = ac[1] + by;
                    b1s[(rl + 8) * 4 + l]     = ac[2] + bx;
                    b1s[(rl + 8) * 4 + l + 1] = ac[3] + by;
                }
            }
        }
    }
}

__global__ void __launch_bounds__(NTHR, 2)
ib_mma(const float* __restrict__ x, const float* __restrict__ chi,
       const float* __restrict__ W, const float* __restrict__ b,
       float* __restrict__ a1, float* __restrict__ co,
       long long n, long long T)
{
    extern __shared__ char sm[];
    float* bs  = (float*)(sm + SM_BS);
    float* b1s = (float*)(sm + SM_B1S);
    unsigned short* whp = (unsigned short*)(sm + SM_WH);
    unsigned short* wlp = (unsigned short*)(sm + SM_WL);

    const int tid = threadIdx.x, wid = tid >> 5, lane = tid & 31;
    const uint32_t smb = smem_u32(sm);
    const uint32_t yhb = smb + SM_YH, ylb = smb + SM_YL;
    const uint32_t whb = smb + SM_WH, wlb = smb + SM_WL;

    // ---- stage W^T (hi/lo bf16) + bias, once ----
    for (int i = tid; i < KBE * KBE; i += NTHR) {
        int nn = i % KBE, kk = i / KBE;
        float w = (nn < CDIM && kk < CDIM) ? W[kk * CDIM + nn] : 0.f;
        unsigned short h, l;
        split(w, h, l);
        whp[nn * KBE + kk] = h;
        wlp[nn * KBE + kk] = l;
    }
    for (int i = tid; i < KBE; i += NTHR) bs[i] = (i < CDIM) ? b[i] : 0.f;
    __syncthreads();

    // ---- per-warp ldmatrix offsets ----
    const int mrow = (wid & 1) * 32;
    const int cw   = wid >> 1;               // 0: groups 0..8, 1: groups 9..16
    const int j3 = lane >> 3, rw = lane & 7;
    const int qr = lane >> 2, qc = lane & 3;
    const int g0 = cw ? 9 : 0;

    Offs o;
    o.aoff = (uint32_t)((mrow + ((j3 & 1) << 3) + rw) * RSTR + ((j3 >> 1) << 4));
    #pragma unroll
    for (int p = 0; p < 4; ++p) {
        int g = g0 + 2 * p;
        o.bpo[p]  = (uint32_t)((g * 8 + ((j3 >> 1) << 3) + rw) * RSTR + ((j3 & 1) << 4));
        o.b8po[p] = (uint32_t)((g * 8 + ((j3 & 1) << 3) + rw) * RSTR + 256);
    }
    o.b16s = (uint32_t)((64 + rw) * RSTR + ((j3 & 1) << 4));
    o.b8s  = (uint32_t)((64 + rw) * RSTR + 256);

    // staging / chi mapping
    const int r2 = tid >> 1, hh = tid & 1;
    const int grid = gridDim.x;

    for (long long t = blockIdx.x; t < T; t += grid) {
        const long long row0 = t * TILE;
        const long long row = row0 + r2;
        const bool ok = row < n;

        // ---- stage y (x part) ----
        {
            const float* xp = x + row * FDIM + hh * 64;
            unsigned short* dsth = (unsigned short*)(sm + SM_YH) + r2 * KBE + hh * 64;
            unsigned short* dstl = (unsigned short*)(sm + SM_YL) + r2 * KBE + hh * 64;
            #pragma unroll
            for (int c = 0; c < 8; ++c) {
                float4 va = ok ? *(const float4*)(xp + c * 8)     : make_float4(0, 0, 0, 0);
                float4 vb = ok ? *(const float4*)(xp + c * 8 + 4) : make_float4(0, 0, 0, 0);
                uint4 hv, lv;
                sp2(va.x, va.y, hv.x, lv.x);
                sp2(va.z, va.w, hv.y, lv.y);
                sp2(vb.x, vb.y, hv.z, lv.z);
                sp2(vb.z, vb.w, hv.w, lv.w);
                *(uint4*)(dsth + c * 8) = hv;
                *(uint4*)(dstl + c * 8) = lv;
            }
        }

        // ---- chi + d_chi ----
        float cvx[8];
        {
            const float4* cp = (const float4*)(chi + row * 16 + hh * 8);
            float4 ca = ok ? cp[0] : make_float4(0, 0, 0, 0);
            float4 cb = ok ? cp[1] : make_float4(0, 0, 0, 0);
            cvx[0] = ca.x; cvx[1] = ca.y; cvx[2] = ca.z; cvx[3] = ca.w;
            cvx[4] = cb.x; cvx[5] = cb.y; cvx[6] = cb.z; cvx[7] = cb.w;

            float qa = ca.x * ca.x;
            float qb = ca.y * ca.y + ca.z * ca.z + ca.w * ca.w;
            float qc2 = cb.x * cb.x + cb.y * cb.y + cb.z * cb.z + cb.w * cb.w;
            float s0, s1, s2, s3;
            if (hh == 0) { s0 = qa;  s1 = qb;  s2 = qc2; s3 = 0.f; }
            else         { s0 = 0.f; s1 = 0.f; s2 = qa;  s3 = qb + qc2; }
            s0 += __shfl_xor_sync(0xFFFFFFFFu, s0, 1);
            s1 += __shfl_xor_sync(0xFFFFFFFFu, s1, 1);
            s2 += __shfl_xor_sync(0xFFFFFFFFu, s2, 1);
            s3 += __shfl_xor_sync(0xFFFFFFFFu, s3, 1);

            uint32_t h0, l0, h1, l1;
            sp2(s0, s1, h0, l0);
            sp2(s2, s3, h1, l1);
            if (hh == 0)
                *(uint4*)(sm + SM_YH + r2 * RSTR + 256) = make_uint4(h0, h1, 0u, 0u);
            else
                *(uint4*)(sm + SM_YL + r2 * RSTR + 256) = make_uint4(l0, l1, 0u, 0u);
        }
        __syncthreads();

        // ---- MMA + a1/b1 epilogue ----
        if (cw == 0)
            compute_tile<0>(yhb, ylb, whb, wlb, o, bs, b1s, a1, row0, n, mrow, qr, qc);
        else
            compute_tile<1>(yhb, ylb, whb, wlb, o, bs, b1s, a1, row0, n, mrow, qr, qc);
        __syncthreads();

        // ---- chi_out ----
        if (ok) {
            float4 bv = ((const float4*)b1s)[r2];
            float o8[8];
            if (hh == 0) {
                o8[0] = bv.x * cvx[0];
                o8[1] = bv.y * cvx[1]; o8[2] = bv.y * cvx[2]; o8[3] = bv.y * cvx[3];
                o8[4] = bv.z * cvx[4]; o8[5] = bv.z * cvx[5];
                o8[6] = bv.z * cvx[6]; o8[7] = bv.z * cvx[7];
            } else {
                o8[0] = bv.z * cvx[0];
                #pragma unroll
                for (int m = 1; m < 8; ++m) o8[m] = bv.w * cvx[m];
            }
            float4* dst = (float4*)(co + row * 16 + hh * 8);
            dst[0] = make_float4(o8[0], o8[1], o8[2], o8[3]);
            dst[1] = make_float4(o8[4], o8[5], o8[6], o8[7]);
        }
        __syncthreads();
    }
}

extern "C" void kernel_launch(void* const* d_in, const int* in_sizes, int n_in,
                              void* d_out, int out_size)
{
    int ix = 0, ichi = 1, iW = 3, ib_ = 4;
    long long maxsz = -1;
    for (int i = 0; i < n_in; ++i)
        if ((long long)in_sizes[i] > maxsz) { maxsz = in_sizes[i]; ix = i; }
    long long n = maxsz / FDIM;
    for (int i = 0; i < n_in; ++i) {
        long long s = in_sizes[i];
        if (i == ix) continue;
        if (s == CDIM * CDIM) iW = i;
        else if (s == CDIM)   ib_ = i;
        else if (s == 16 * n) ichi = i;
    }
    const float* x   = (const float*)d_in[ix];
    const float* chi = (const float*)d_in[ichi];
    const float* W   = (const float*)d_in[iW];
    const float* b   = (const float*)d_in[ib_];
    float* a1 = (float*)d_out;
    float* co = a1 + (size_t)n * FDIM;

    long long T = (n + TILE - 1) / TILE;
    int sms = 148;
    cudaDeviceGetAttribute(&sms, cudaDevAttrMultiProcessorCount, 0);
    long long g = 2LL * sms;
    int grid = (int)(T < g ? T : g);

    cudaFuncSetAttribute(ib_mma, cudaFuncAttributeMaxDynamicSharedMemorySize, SMEM_BYTES);
    ib_mma<<<grid, NTHR, SMEM_BYTES>>>(x, chi, W, b, a1, co, n, T);
}

// round 9
// speedup vs baseline: 3.1459x; 1.0726x over previous
#include <cuda_runtime.h>
#include <cuda_bf16.h>
#include <cstdint>

#define FDIM 128
#define CDIM 132
#define KBE  136          // padded K in bf16 elements
#define RSTR 272          // bytes per smem row (136 bf16)
#define TILE 64
#define NTHR 128

// smem byte offsets
#define SM_BS   0                          // bias: 136 floats
#define SM_B1S  1024                       // b1 buffer: 64 x 4 floats
#define SM_YH   2048
#define SM_YL   (SM_YH + TILE * RSTR)      // 19456
#define SM_WH   (SM_YL + TILE * RSTR)      // 36864
#define SM_WL   (SM_WH + KBE * RSTR)       // 73856
#define SMEM_BYTES (SM_WL + KBE * RSTR)    // 110848

static __device__ __forceinline__ uint32_t smem_u32(const void* p) {
    uint32_t a;
    asm("{ .reg .u64 t; cvta.to.shared.u64 t, %1; cvt.u32.u64 %0, t; }" : "=r"(a) : "l"(p));
    return a;
}
static __device__ __forceinline__ void split(float v, unsigned short& h, unsigned short& l) {
    __nv_bfloat16 hb = __float2bfloat16(v);
    float r = v - __bfloat162float(hb);
    __nv_bfloat16 lb = __float2bfloat16(r);
    h = __bfloat16_as_ushort(hb);
    l = __bfloat16_as_ushort(lb);
}
// packed split: a -> lower half, b -> upper half
static __device__ __forceinline__ void sp2(float a, float b, uint32_t& h, uint32_t& l) {
    uint32_t hp;
    asm("cvt.rn.bf16x2.f32 %0, %1, %2;" : "=r"(hp) : "f"(b), "f"(a));
    float ha = __uint_as_float(hp << 16);
    float hb = __uint_as_float(hp & 0xFFFF0000u);
    float la = a - ha;
    float lb = b - hb;
    uint32_t lp;
    asm("cvt.rn.bf16x2.f32 %0, %1, %2;" : "=r"(lp) : "f"(lb), "f"(la));
    h = hp; l = lp;
}

static __device__ __forceinline__ void ldsm4(uint32_t a, uint32_t* r) {
    asm volatile("ldmatrix.sync.aligned.m8n8.x4.shared.b16 {%0,%1,%2,%3}, [%4];"
        : "=r"(r[0]), "=r"(r[1]), "=r"(r[2]), "=r"(r[3]) : "r"(a));
}
static __device__ __forceinline__ void ldsm2(uint32_t a, uint32_t* r) {
    asm volatile("ldmatrix.sync.aligned.m8n8.x2.shared.b16 {%0,%1}, [%2];"
        : "=r"(r[0]), "=r"(r[1]) : "r"(a));
}
static __device__ __forceinline__ void ldsm1(uint32_t a, uint32_t* r) {
    asm volatile("ldmatrix.sync.aligned.m8n8.x1.shared.b16 {%0}, [%1];"
        : "=r"(r[0]) : "r"(a));
}
static __device__ __forceinline__ void mma16(float* c, const uint32_t* A, const uint32_t* B) {
    asm volatile("mma.sync.aligned.m16n8k16.row.col.f32.bf16.bf16.f32 "
        "{%0,%1,%2,%3}, {%4,%5,%6,%7}, {%8,%9}, {%0,%1,%2,%3};"
        : "+f"(c[0]), "+f"(c[1]), "+f"(c[2]), "+f"(c[3])
        : "r"(A[0]), "r"(A[1]), "r"(A[2]), "r"(A[3]), "r"(B[0]), "r"(B[1]));
}
static __device__ __forceinline__ void mma8(float* c, const uint32_t* A, uint32_t B) {
    asm volatile("mma.sync.aligned.m16n8k8.row.col.f32.bf16.bf16.f32 "
        "{%0,%1,%2,%3}, {%4,%5}, {%6}, {%0,%1,%2,%3};"
        : "+f"(c[0]), "+f"(c[1]), "+f"(c[2]), "+f"(c[3])
        : "r"(A[0]), "r"(A[1]), "r"(B));
}

struct Offs {
    uint32_t aoff;
    uint32_t bpo[4];
    uint32_t b16s;
    uint32_t b8po[4];
    uint32_t b8s;
};

template<int NG> struct Frag {
    uint32_t Ah0[4], Ah1[4], Al0[4], Al1[4];
    uint32_t Bh[NG][2], Bl[NG][2];
};

template<int NG>
static __device__ __forceinline__ void load_frag(
    int s, uint32_t yhb, uint32_t ylb, uint32_t whb, uint32_t wlb,
    const Offs& o, Frag<NG>& F)
{
    const uint32_t kb = (uint32_t)s * 32;
    ldsm4(yhb + o.aoff + kb, F.Ah0);
    ldsm4(yhb + o.aoff + 4352 + kb, F.Ah1);
    ldsm4(ylb + o.aoff + kb, F.Al0);
    ldsm4(ylb + o.aoff + 4352 + kb, F.Al1);
    #pragma unroll
    for (int p = 0; p < NG / 2; ++p) {
        uint32_t r[4];
        ldsm4(whb + o.bpo[p] + kb, r);
        F.Bh[2*p][0] = r[0]; F.Bh[2*p][1] = r[1];
        F.Bh[2*p+1][0] = r[2]; F.Bh[2*p+1][1] = r[3];
        ldsm4(wlb + o.bpo[p] + kb, r);
        F.Bl[2*p][0] = r[0]; F.Bl[2*p][1] = r[1];
        F.Bl[2*p+1][0] = r[2]; F.Bl[2*p+1][1] = r[3];
    }
    if (NG & 1) {
        ldsm2(whb + o.b16s + kb, F.Bh[NG-1]);
        ldsm2(wlb + o.b16s + kb, F.Bl[NG-1]);
    }
}

template<int NG>
static __device__ __forceinline__ void issue_mma(const Frag<NG>& F, float (*acc)[4])
{
    #pragma unroll
    for (int g = 0; g < NG; ++g) {
        mma16(acc[g],      F.Ah0, F.Bh[g]);
        mma16(acc[NG + g], F.Ah1, F.Bh[g]);
    }
    #pragma unroll
    for (int g = 0; g < NG; ++g) {
        mma16(acc[g],      F.Ah0, F.Bl[g]);
        mma16(acc[NG + g], F.Ah1, F.Bl[g]);
    }
    #pragma unroll
    for (int g = 0; g < NG; ++g) {
        mma16(acc[g],      F.Al0, F.Bh[g]);
        mma16(acc[NG + g], F.Al1, F.Bh[g]);
    }
}

template<int CW>
static __device__ __forceinline__ void compute_tile(
    uint32_t yhb, uint32_t ylb, uint32_t whb, uint32_t wlb,
    const Offs& o, const float* bs, float* b1s,
    float* __restrict__ a1, long long row0, long long n,
    int mrow, int qr, int qc)
{
    constexpr int NG = CW ? 8 : 9;
    constexpr int G0 = CW ? 9 : 0;

    float acc[2 * NG][4];
    #pragma unroll
    for (int i = 0; i < 2 * NG; ++i)
        #pragma unroll
        for (int j = 0; j < 4; ++j) acc[i][j] = 0.f;

    // ---- software-pipelined k16 steps ----
    Frag<NG> f0, f1;
    load_frag<NG>(0, yhb, ylb, whb, wlb, o, f0);
    #pragma unroll
    for (int s = 0; s < 8; s += 2) {
        if (s + 1 < 8) load_frag<NG>(s + 1, yhb, ylb, whb, wlb, o, f1);
        issue_mma<NG>(f0, acc);
        if (s + 2 < 8) load_frag<NG>(s + 2, yhb, ylb, whb, wlb, o, f0);
        if (s + 1 < 8) issue_mma<NG>(f1, acc);
    }

    // ---- k8 tail: k = 128..135 ----
    {
        uint32_t Ah0[2], Ah1[2], Al0[2], Al1[2];
        ldsm2(yhb + o.aoff + 256, Ah0);
        ldsm2(yhb + o.aoff + 4352 + 256, Ah1);
        ldsm2(ylb + o.aoff + 256, Al0);
        ldsm2(ylb + o.aoff + 4352 + 256, Al1);
        uint32_t B8h[NG], B8l[NG];
        #pragma unroll
        for (int p = 0; p < NG / 2; ++p) {
            uint32_t r[2];
            ldsm2(whb + o.b8po[p], r);
            B8h[2*p] = r[0]; B8h[2*p+1] = r[1];
            ldsm2(wlb + o.b8po[p], r);
            B8l[2*p] = r[0]; B8l[2*p+1] = r[1];
        }
        if (NG & 1) {
            uint32_t r[1];
            ldsm1(whb + o.b8s, r); B8h[NG-1] = r[0];
            ldsm1(wlb + o.b8s, r); B8l[NG-1] = r[0];
        }
        #pragma unroll
        for (int g = 0; g < NG; ++g) {
            mma8(acc[g],      Ah0, B8h[g]);
            mma8(acc[NG + g], Ah1, B8h[g]);
            mma8(acc[g],      Ah0, B8l[g]);
            mma8(acc[NG + g], Ah1, B8l[g]);
            mma8(acc[g],      Al0, B8h[g]);
            mma8(acc[NG + g], Al1, B8h[g]);
        }
    }

    // ---- epilogue ----
    #pragma unroll
    for (int f = 0; f < 2; ++f) {
        #pragma unroll
        for (int g = 0; g < NG; ++g) {
            const int ga = G0 + g;
            const float* ac = acc[f * NG + g];
            const int colg = ga * 8 + qc * 2;
            if (ga < 16) {
                float bx = bs[colg], by = bs[colg + 1];
                long long r1 = row0 + mrow + f * 16 + qr;
                if (r1 < n)
                    *(float2*)(a1 + r1 * FDIM + colg) = make_float2(ac[0] + bx, ac[1] + by);
                if (r1 + 8 < n)
                    *(float2*)(a1 + (r1 + 8) * FDIM + colg) = make_float2(ac[2] + bx, ac[3] + by);
            } else if (ga == 16) {
                if (qc < 2) {
                    int l = qc * 2;
                    float bx = bs[FDIM + l], by = bs[FDIM + l + 1];
                    int rl = mrow + f * 16 + qr;
                    b1s[rl * 4 + l]       = ac[0] + bx;
                    b1s[rl * 4 + l + 1]   = ac[1] + by;
                    b1s[(rl + 8) * 4 + l]     = ac[2] + bx;
                    b1s[(rl + 8) * 4 + l + 1] = ac[3] + by;
                }
            }
        }
    }
}

// stage y (x part + d_chi) for one tile; returns this thread's chi values in cvx
static __device__ __forceinline__ void stage_tile(
    const float* __restrict__ x, const float* __restrict__ chi,
    char* sm, long long row, bool ok, int r2, int hh, float* cvx)
{
    {
        const float* xp = x + row * FDIM + hh * 64;
        unsigned short* dsth = (unsigned short*)(sm + SM_YH) + r2 * KBE + hh * 64;
        unsigned short* dstl = (unsigned short*)(sm + SM_YL) + r2 * KBE + hh * 64;
        #pragma unroll
        for (int c = 0; c < 8; ++c) {
            float4 va = ok ? *(const float4*)(xp + c * 8)     : make_float4(0, 0, 0, 0);
            float4 vb = ok ? *(const float4*)(xp + c * 8 + 4) : make_float4(0, 0, 0, 0);
            uint4 hv, lv;
            sp2(va.x, va.y, hv.x, lv.x);
            sp2(va.z, va.w, hv.y, lv.y);
            sp2(vb.x, vb.y, hv.z, lv.z);
            sp2(vb.z, vb.w, hv.w, lv.w);
            *(uint4*)(dsth + c * 8) = hv;
            *(uint4*)(dstl + c * 8) = lv;
        }
    }
    {
        const float4* cp = (const float4*)(chi + row * 16 + hh * 8);
        float4 ca = ok ? cp[0] : make_float4(0, 0, 0, 0);
        float4 cb = ok ? cp[1] : make_float4(0, 0, 0, 0);
        cvx[0] = ca.x; cvx[1] = ca.y; cvx[2] = ca.z; cvx[3] = ca.w;
        cvx[4] = cb.x; cvx[5] = cb.y; cvx[6] = cb.z; cvx[7] = cb.w;

        float qa = ca.x * ca.x;
        float qb = ca.y * ca.y + ca.z * ca.z + ca.w * ca.w;
        float qc2 = cb.x * cb.x + cb.y * cb.y + cb.z * cb.z + cb.w * cb.w;
        float s0, s1, s2, s3;
        if (hh == 0) { s0 = qa;  s1 = qb;  s2 = qc2; s3 = 0.f; }
        else         { s0 = 0.f; s1 = 0.f; s2 = qa;  s3 = qb + qc2; }
        s0 += __shfl_xor_sync(0xFFFFFFFFu, s0, 1);
        s1 += __shfl_xor_sync(0xFFFFFFFFu, s1, 1);
        s2 += __shfl_xor_sync(0xFFFFFFFFu, s2, 1);
        s3 += __shfl_xor_sync(0xFFFFFFFFu, s3, 1);

        uint32_t h0, l0, h1, l1;
        sp2(s0, s1, h0, l0);
        sp2(s2, s3, h1, l1);
        if (hh == 0)
            *(uint4*)(sm + SM_YH + r2 * RSTR + 256) = make_uint4(h0, h1, 0u, 0u);
        else
            *(uint4*)(sm + SM_YL + r2 * RSTR + 256) = make_uint4(l0, l1, 0u, 0u);
    }
}

static __device__ __forceinline__ void chi_out_store(
    float* __restrict__ co, const float* b1s, const float* cvx,
    long long row, bool ok, int r2, int hh)
{
    if (!ok) return;
    float4 bv = ((const float4*)b1s)[r2];
    float o8[8];
    if (hh == 0) {
        o8[0] = bv.x * cvx[0];
        o8[1] = bv.y * cvx[1]; o8[2] = bv.y * cvx[2]; o8[3] = bv.y * cvx[3];
        o8[4] = bv.z * cvx[4]; o8[5] = bv.z * cvx[5];
        o8[6] = bv.z * cvx[6]; o8[7] = bv.z * cvx[7];
    } else {
        o8[0] = bv.z * cvx[0];
        #pragma unroll
        for (int m = 1; m < 8; ++m) o8[m] = bv.w * cvx[m];
    }
    float4* dst = (float4*)(co + row * 16 + hh * 8);
    dst[0] = make_float4(o8[0], o8[1], o8[2], o8[3]);
    dst[1] = make_float4(o8[4], o8[5], o8[6], o8[7]);
}

__global__ void __launch_bounds__(NTHR, 2)
ib_mma(const float* __restrict__ x, const float* __restrict__ chi,
       const float* __restrict__ W, const float* __restrict__ b,
       float* __restrict__ a1, float* __restrict__ co,
       long long n, long long T)
{
    extern __shared__ char sm[];
    float* bs  = (float*)(sm + SM_BS);
    float* b1s = (float*)(sm + SM_B1S);
    unsigned short* whp = (unsigned short*)(sm + SM_WH);
    unsigned short* wlp = (unsigned short*)(sm + SM_WL);

    const int tid = threadIdx.x, wid = tid >> 5, lane = tid & 31;
    const uint32_t smb = smem_u32(sm);
    const uint32_t yhb = smb + SM_YH, ylb = smb + SM_YL;
    const uint32_t whb = smb + SM_WH, wlb = smb + SM_WL;

    // ---- stage W^T (hi/lo bf16) + bias, once ----
    for (int i = tid; i < KBE * KBE; i += NTHR) {
        int nn = i % KBE, kk = i / KBE;
        float w = (nn < CDIM && kk < CDIM) ? W[kk * CDIM + nn] : 0.f;
        unsigned short h, l;
        split(w, h, l);
        whp[nn * KBE + kk] = h;
        wlp[nn * KBE + kk] = l;
    }
    for (int i = tid; i < KBE; i += NTHR) bs[i] = (i < CDIM) ? b[i] : 0.f;

    // ---- per-warp ldmatrix offsets ----
    const int mrow = (wid & 1) * 32;
    const int cw   = wid >> 1;
    const int j3 = lane >> 3, rw = lane & 7;
    const int qr = lane >> 2, qc = lane & 3;
    const int g0 = cw ? 9 : 0;

    Offs o;
    o.aoff = (uint32_t)((mrow + ((j3 & 1) << 3) + rw) * RSTR + ((j3 >> 1) << 4));
    #pragma unroll
    for (int p = 0; p < 4; ++p) {
        int g = g0 + 2 * p;
        o.bpo[p]  = (uint32_t)((g * 8 + ((j3 >> 1) << 3) + rw) * RSTR + ((j3 & 1) << 4));
        o.b8po[p] = (uint32_t)((g * 8 + ((j3 & 1) << 3) + rw) * RSTR + 256);
    }
    o.b16s = (uint32_t)((64 + rw) * RSTR + ((j3 & 1) << 4));
    o.b8s  = (uint32_t)((64 + rw) * RSTR + 256);

    const int r2 = tid >> 1, hh = tid & 1;
    const int grid = gridDim.x;

    // ---- preamble: stage first tile ----
    float cvx[8];
    {
        long long row = blockIdx.x * (long long)TILE + r2;
        stage_tile(x, chi, sm, row, (blockIdx.x < T) && (row < n), r2, hh, cvx);
    }
    __syncthreads();

    for (long long t = blockIdx.x; t < T; t += grid) {
        const long long row0 = t * TILE;

        // ---- MMA + a1/b1 epilogue ----
        if (cw == 0)
            compute_tile<0>(yhb, ylb, whb, wlb, o, bs, b1s, a1, row0, n, mrow, qr, qc);
        else
            compute_tile<1>(yhb, ylb, whb, wlb, o, bs, b1s, a1, row0, n, mrow, qr, qc);
        __syncthreads();

        // ---- overlap: stage(t+grid) + chi_out(t) ----
        const long long t2 = t + grid;
        float cvn[8];
        if (t2 < T) {
            long long row2 = t2 * TILE + r2;
            stage_tile(x, chi, sm, row2, row2 < n, r2, hh, cvn);
        }
        chi_out_store(co, b1s, cvx, row0 + r2, row0 + r2 < n, r2, hh);
        #pragma unroll
        for (int m = 0; m < 8; ++m) cvx[m] = cvn[m];
        __syncthreads();
    }
}

extern "C" void kernel_launch(void* const* d_in, const int* in_sizes, int n_in,
                              void* d_out, int out_size)
{
    int ix = 0, ichi = 1, iW = 3, ib_ = 4;
    long long maxsz = -1;
    for (int i = 0; i < n_in; ++i)
        if ((long long)in_sizes[i] > maxsz) { maxsz = in_sizes[i]; ix = i; }
    long long n = maxsz / FDIM;
    for (int i = 0; i < n_in; ++i) {
        long long s = in_sizes[i];
        if (i == ix) continue;
        if (s == CDIM * CDIM) iW = i;
        else if (s == CDIM)   ib_ = i;
        else if (s == 16 * n) ichi = i;
    }
    const float* x   = (const float*)d_in[ix];
    const float* chi = (const float*)d_in[ichi];
    const float* W   = (const float*)d_in[iW];
    const float* b   = (const float*)d_in[ib_];
    float* a1 = (float*)d_out;
    float* co = a1 + (size_t)n * FDIM;

    long long T = (n + TILE - 1) / TILE;
    int sms = 148;
    cudaDeviceGetAttribute(&sms, cudaDevAttrMultiProcessorCount, 0);
    long long g = 2LL * sms;
    int grid = (int)(T < g ? T : g);

    cudaFuncSetAttribute(ib_mma, cudaFuncAttributeMaxDynamicSharedMemorySize, SMEM_BYTES);
    ib_mma<<<grid, NTHR, SMEM_BYTES>>>(x, chi, W, b, a1, co, n, T);
}